// round 13
// baseline (speedup 1.0000x reference)
#include <cuda_runtime.h>
#include <math.h>

#define B 16
#define C 3
#define H 512
#define W 512
#define HW (H*W)
#define CHW (C*H*W)
#define KPOOL 15

#define TXV 128      // output tile width
#define TY  32       // output tile height
#define NW  8        // warps per block
#define HR  46       // halo rows (TY + 14)
#define MW  160      // m-tile width (TXV + 16 halo cols = 5*32)
#define NQUAD (HR * (MW/4))          // 1840 detector quads
#define NBLK ((W/TXV)*(H/(2*TY))*B)  // 4*8*16 = 512 blocks, 2 tiles each

// scalar accumulators: S1 (l1), S2w (al1*wm), S3 (color)
__device__ double g_acc[3];
__device__ unsigned g_ticket;

__device__ __forceinline__ float fast_tanh(float x) {
    float r;
    asm("tanh.approx.f32 %0, %1;" : "=f"(r) : "f"(x));
    return r;
}
__device__ __forceinline__ float fsig2(float half_x) {   // sigmoid(2*half_x)
    return fmaf(0.5f, fast_tanh(half_x), 0.5f);
}

__device__ __forceinline__ float detector(float r, float g, float b) {
    float lum = 0.299f * r + 0.587f * g + 0.114f * b;
    float mx = fmaxf(r, fmaxf(g, b));
    float mn = fminf(r, fminf(g, b));
    // src rescaled to [0,1]: sigmoid(10*lum-3) * sigmoid(3-10*(mx-mn))
    return fsig2(5.0f * lum - 1.5f) * fsig2(1.5f - 5.0f * (mx - mn));
}

__device__ __forceinline__ float4 ldcs4(const float* p) {
    return __ldcs((const float4*)p);
}

__global__ __launch_bounds__(256, 3) void k_fused(const float* __restrict__ pred,
                                                  const float* __restrict__ tgt,
                                                  const float* __restrict__ src,
                                                  float* __restrict__ out) {
    const int tx = threadIdx.x;           // 0..31
    const int ty = threadIdx.y;           // 0..7 (warp id)
    const int tid = ty * 32 + tx;
    const int b  = blockIdx.z;
    const int x0 = blockIdx.x * TXV;
    const int y0base = blockIdx.y * (2 * TY);   // two vertically adjacent tiles
    const int xb = x0 - 8;                // m-tile col 0 == global x xb

    __shared__ float mt[HR][MW];          // detector -> prefix -> hsum (in place)

    const size_t base = (size_t)b * CHW;
    const int yl0 = 4 * ty;
    const int xc  = x0 + 4 * tx;

    float a1 = 0.0f, a2 = 0.0f, a3 = 0.0f;   // S1, sum(al1*wm), color

    // ---- Pre-issue tile-0 phase-3 row-0 loads (in flight through phases 1-2) ----
    size_t idx0 = base + (size_t)(y0base + yl0) * W + xc;
    float4 p0 = ldcs4(pred + idx0);
    float4 p1 = ldcs4(pred + idx0 + HW);
    float4 p2 = ldcs4(pred + idx0 + 2 * HW);
    float4 t0 = ldcs4(tgt + idx0);
    float4 t1 = ldcs4(tgt + idx0 + HW);
    float4 t2 = ldcs4(tgt + idx0 + 2 * HW);
    float4 q0 = *(const float4*)(src + idx0);
    float4 q1 = *(const float4*)(src + idx0 + HW);
    float4 q2 = *(const float4*)(src + idx0 + 2 * HW);

#pragma unroll 1
    for (int t = 0; t < 2; ++t) {
        const int y0 = y0base + t * TY;
        if (t) __syncthreads();           // protect mt reuse across tiles

        // ---- Phase 1: detector map with halo (software-pipelined loads) ----
        {
            int i = tid;
            float4 cr, cg, cb;
            bool valid = false;
            int rcur = 0, qcur = 0;
            {
                int r = i / (MW / 4);
                int q = i - r * (MW / 4);
                int y = y0 + r - 7;
                int xg = xb + 4 * q;
                rcur = r; qcur = q;
                valid = ((unsigned)y < H && (unsigned)xg < W);
                if (valid) {
                    size_t idx = base + (size_t)y * W + xg;
                    cr = *(const float4*)(src + idx);
                    cg = *(const float4*)(src + idx + HW);
                    cb = *(const float4*)(src + idx + 2 * HW);
                }
            }
#pragma unroll
            for (int step = 0; step < 8; ++step) {
                int inext = i + 256;
                float4 nr, ng, nb;
                bool nvalid = false;
                int rnext = 0, qnext = 0;
                if (inext < NQUAD) {
                    int r = inext / (MW / 4);
                    int q = inext - r * (MW / 4);
                    int y = y0 + r - 7;
                    int xg = xb + 4 * q;
                    rnext = r; qnext = q;
                    nvalid = ((unsigned)y < H && (unsigned)xg < W);
                    if (nvalid) {
                        size_t idx = base + (size_t)y * W + xg;
                        nr = *(const float4*)(src + idx);
                        ng = *(const float4*)(src + idx + HW);
                        nb = *(const float4*)(src + idx + 2 * HW);
                    }
                }
                if (i < NQUAD) {
                    float4 m4 = make_float4(0.f, 0.f, 0.f, 0.f);
                    if (valid) {
                        m4.x = detector(cr.x, cg.x, cb.x);
                        m4.y = detector(cr.y, cg.y, cb.y);
                        m4.z = detector(cr.z, cg.z, cb.z);
                        m4.w = detector(cr.w, cg.w, cb.w);
                    }
                    *(float4*)&mt[rcur][4 * qcur] = m4;
                }
                i = inext; valid = nvalid; rcur = rnext; qcur = qnext;
                cr = nr; cg = ng; cb = nb;
            }
        }
        __syncthreads();

        // ---- Phase 2: per-row horizontal pool via in-warp prefix scan ----
        for (int r = ty; r < HR; r += NW) {
            int c = 5 * tx;
            float v0 = mt[r][c + 0];
            float v1 = mt[r][c + 1];
            float v2 = mt[r][c + 2];
            float v3 = mt[r][c + 3];
            float v4 = mt[r][c + 4];
            v1 += v0; v2 += v1; v3 += v2; v4 += v3;   // local inclusive prefix
            float s = v4;
#pragma unroll
            for (int o = 1; o < 32; o <<= 1) {
                float n = __shfl_up_sync(0xffffffffu, s, o);
                if (tx >= o) s += n;
            }
            float excl = s - v4;
            mt[r][c + 0] = excl + v0;
            mt[r][c + 1] = excl + v1;
            mt[r][c + 2] = excl + v2;
            mt[r][c + 3] = excl + v3;
            mt[r][c + 4] = excl + v4;
            __syncwarp();
            float h0 = mt[r][tx + 15]       - mt[r][tx];
            float h1 = mt[r][tx + 32 + 15]  - mt[r][tx + 32];
            float h2 = mt[r][tx + 64 + 15]  - mt[r][tx + 64];
            float h3 = mt[r][tx + 96 + 15]  - mt[r][tx + 96];
            __syncwarp();
            mt[r][tx]      = h0;    // hsum row now lives at cols 0..127
            mt[r][tx + 32] = h1;
            mt[r][tx + 64] = h2;
            mt[r][tx + 96] = h3;
        }
        __syncthreads();

        // ---- Phase 3: vertical 15-tap running sum + per-pixel loss ----
        float vs0 = 0.f, vs1 = 0.f, vs2 = 0.f, vs3 = 0.f;
#pragma unroll
        for (int d = 0; d < KPOOL; ++d) {
            float4 h = *(float4*)&mt[yl0 + d][4 * tx];
            vs0 += h.x; vs1 += h.y; vs2 += h.z; vs3 += h.w;
        }

#pragma unroll
        for (int i = 0; i < 4; ++i) {
            // Prefetch next row (distance 1). At i==3 prefetch NEXT TILE's row 0
            // (t==0 only) so tile 1's phases 1-2 run with loss loads in flight.
            float4 np0, np1, np2, nt0, nt1, nt2, nq0, nq1, nq2;
            bool havenext = (i < 3) || (t == 0);
            if (havenext) {
                size_t nidx = (i < 3)
                    ? base + (size_t)(y0 + yl0 + i + 1) * W + xc
                    : base + (size_t)(y0 + TY + yl0) * W + xc;
                np0 = ldcs4(pred + nidx);
                np1 = ldcs4(pred + nidx + HW);
                np2 = ldcs4(pred + nidx + 2 * HW);
                nt0 = ldcs4(tgt + nidx);
                nt1 = ldcs4(tgt + nidx + HW);
                nt2 = ldcs4(tgt + nidx + 2 * HW);
                nq0 = *(const float4*)(src + nidx);
                nq1 = *(const float4*)(src + nidx + HW);
                nq2 = *(const float4*)(src + nidx + 2 * HW);
            }

            const float* P0 = &p0.x; const float* P1 = &p1.x; const float* P2 = &p2.x;
            const float* T0 = &t0.x; const float* T1 = &t1.x; const float* T2 = &t2.x;
            const float* Q0 = &q0.x; const float* Q1 = &q1.x; const float* Q2 = &q2.x;
            float wmv[4] = {vs0, vs1, vs2, vs3};

#pragma unroll
            for (int k = 0; k < 4; ++k) {
                float d0 = P0[k] - T0[k], d1 = P1[k] - T1[k], d2 = P2[k] - T2[k];
                float al1 = fabsf(d0) + fabsf(d1) + fabsf(d2);
                float wm = wmv[k] * (1.0f / 225.0f);
                a1 += al1;
                a2 += al1 * wm;

                float st0 = T0[k] - Q0[k], st1 = T1[k] - Q1[k], st2 = T2[k] - Q2[k];
                float sp0 = P0[k] - Q0[k], sp1 = P1[k] - Q1[k], sp2 = P2[k] - Q2[k];
                float stm2 = fmaxf(st0 * st0 + st1 * st1 + st2 * st2, 1e-24f);
                float spm2 = fmaxf(sp0 * sp0 + sp1 * sp1 + sp2 * sp2, 1e-24f);
                float dot  = st0 * sp0 + st1 * sp1 + st2 * sp2;
                float ii = rsqrtf(fmaxf(stm2 * spm2, 1e-37f));  // 1/(stm*spm)
                float align = dot * ii;
                float magl  = fabsf(spm2 * ii - 1.0f);          // spm/stm
                a3 += wm * (1.0f - align + 0.5f * magl);
            }

            if (i < 3) {   // slide vertical window
                float4 add = *(float4*)&mt[yl0 + i + KPOOL][4 * tx];
                float4 sub = *(float4*)&mt[yl0 + i][4 * tx];
                vs0 += add.x - sub.x; vs1 += add.y - sub.y;
                vs2 += add.z - sub.z; vs3 += add.w - sub.w;
            }
            if (havenext) {   // rotate pipeline registers (incl. cross-tile)
                p0 = np0; p1 = np1; p2 = np2;
                t0 = nt0; t1 = nt1; t2 = nt2;
                q0 = nq0; q1 = nq1; q2 = nq2;
            }
        }
    }

    // ---- Reduction ----
#pragma unroll
    for (int o = 16; o > 0; o >>= 1) {
        a1 += __shfl_down_sync(0xffffffffu, a1, o);
        a2 += __shfl_down_sync(0xffffffffu, a2, o);
        a3 += __shfl_down_sync(0xffffffffu, a3, o);
    }
    __shared__ float red[NW][3];
    __shared__ bool amLast;
    if (tx == 0) { red[ty][0] = a1; red[ty][1] = a2; red[ty][2] = a3; }
    __syncthreads();
    if (ty == 0 && tx == 0) {
        float r1 = 0.0f, r2 = 0.0f, r3 = 0.0f;
#pragma unroll
        for (int w = 0; w < NW; ++w) { r1 += red[w][0]; r2 += red[w][1]; r3 += red[w][2]; }
        atomicAdd(&g_acc[0], (double)r1);
        atomicAdd(&g_acc[1], (double)r2);
        atomicAdd(&g_acc[2], (double)r3);
        __threadfence();
        unsigned tk = atomicAdd(&g_ticket, 1u);
        amLast = (tk == NBLK - 1);
    }
    __syncthreads();

    // ---- Last block folds the final combine ----
    if (amLast && ty == 0 && tx == 0) {
        const double N_ALL = (double)B * C * H * W;
        const double N_PIX = (double)B * H * W;
        double S1 = g_acc[0], S2w = g_acc[1], S3 = g_acc[2];
        // l1 + 3*win_l1 + 2*color ; win_l1 = (S1 + 4*S2w)/N_ALL
        double total = 4.0 * S1 / N_ALL + 12.0 * S2w / N_ALL + 2.0 * S3 / N_PIX;
        out[0] = (float)total;
        g_acc[0] = 0.0; g_acc[1] = 0.0; g_acc[2] = 0.0;
        g_ticket = 0u;
    }
}

extern "C" void kernel_launch(void* const* d_in, const int* in_sizes, int n_in,
                              void* d_out, int out_size) {
    const float* pred = (const float*)d_in[0];
    const float* tgt  = (const float*)d_in[1];
    const float* src  = (const float*)d_in[2];
    float* out = (float*)d_out;

    dim3 grid(W / TXV, H / (2 * TY), B);
    dim3 blk(32, NW);
    k_fused<<<grid, blk>>>(pred, tgt, src, out);
}

// round 14
// speedup vs baseline: 1.8431x; 1.8431x over previous
#include <cuda_runtime.h>
#include <math.h>

#define B 16
#define C 3
#define H 512
#define W 512
#define HW (H*W)
#define CHW (C*H*W)
#define KPOOL 15

#define TXV 128      // output tile width
#define TY  32       // output tile height
#define NW  8        // warps per block
#define HR  46       // halo rows (TY + 14)
#define MW  160      // m-tile width (TXV + 16 halo cols = 5*32)
#define NQUAD (HR * (MW/4))          // 1840 detector quads
#define NBLOCKS ((W/TXV)*(H/TY)*B)   // 1024

// scalar accumulators: S1 (l1), S2w (al1*wm), S3 (color)
__device__ double g_acc[3];
__device__ unsigned g_ticket;

__device__ __forceinline__ float fast_tanh(float x) {
    float r;
    asm("tanh.approx.f32 %0, %1;" : "=f"(r) : "f"(x));
    return r;
}
__device__ __forceinline__ float fsig2(float half_x) {   // sigmoid(2*half_x)
    return fmaf(0.5f, fast_tanh(half_x), 0.5f);
}

__device__ __forceinline__ float detector(float r, float g, float b) {
    float lum = 0.299f * r + 0.587f * g + 0.114f * b;
    float mx = fmaxf(r, fmaxf(g, b));
    float mn = fminf(r, fminf(g, b));
    // src rescaled to [0,1]: sigmoid(10*lum-3) * sigmoid(3-10*(mx-mn))
    return fsig2(5.0f * lum - 1.5f) * fsig2(1.5f - 5.0f * (mx - mn));
}

__device__ __forceinline__ float4 ldcs4(const float* p) {
    return __ldcs((const float4*)p);
}

__global__ __launch_bounds__(256, 4) void k_fused(const float* __restrict__ pred,
                                                  const float* __restrict__ tgt,
                                                  const float* __restrict__ src,
                                                  float* __restrict__ out) {
    const int tx = threadIdx.x;           // 0..31
    const int ty = threadIdx.y;           // 0..7 (warp id)
    const int tid = ty * 32 + tx;
    const int b  = blockIdx.z;
    const int x0 = blockIdx.x * TXV;
    const int y0 = blockIdx.y * TY;
    const int xb = x0 - 8;                // m-tile col 0 == global x xb

    __shared__ float mt[HR][MW];          // detector -> prefix -> hsum (in place)

    const size_t base = (size_t)b * CHW;
    const int yl0 = 4 * ty;
    const int xc  = x0 + 4 * tx;

    // ---- Pre-issue phase-3 row-0 loads: in flight through phases 1-2 ----
    const size_t idx0 = base + (size_t)(y0 + yl0) * W + xc;
    float4 p0 = ldcs4(pred + idx0);
    float4 p1 = ldcs4(pred + idx0 + HW);
    float4 p2 = ldcs4(pred + idx0 + 2 * HW);
    float4 t0 = ldcs4(tgt + idx0);
    float4 t1 = ldcs4(tgt + idx0 + HW);
    float4 t2 = ldcs4(tgt + idx0 + 2 * HW);
    float4 q0 = *(const float4*)(src + idx0);
    float4 q1 = *(const float4*)(src + idx0 + HW);
    float4 q2 = *(const float4*)(src + idx0 + 2 * HW);

    // ---- Phase 1: detector map with halo (software-pipelined loads) ----
    {
        int i = tid;
        float4 cr, cg, cb;
        bool valid = false;
        int rcur = 0, qcur = 0;
        {
            int r = i / (MW / 4);
            int q = i - r * (MW / 4);
            int y = y0 + r - 7;
            int xg = xb + 4 * q;
            rcur = r; qcur = q;
            valid = ((unsigned)y < H && (unsigned)xg < W);
            if (valid) {
                size_t idx = base + (size_t)y * W + xg;
                cr = *(const float4*)(src + idx);
                cg = *(const float4*)(src + idx + HW);
                cb = *(const float4*)(src + idx + 2 * HW);
            }
        }
#pragma unroll
        for (int step = 0; step < 8; ++step) {
            int inext = i + 256;
            float4 nr, ng, nb;
            bool nvalid = false;
            int rnext = 0, qnext = 0;
            if (inext < NQUAD) {
                int r = inext / (MW / 4);
                int q = inext - r * (MW / 4);
                int y = y0 + r - 7;
                int xg = xb + 4 * q;
                rnext = r; qnext = q;
                nvalid = ((unsigned)y < H && (unsigned)xg < W);
                if (nvalid) {
                    size_t idx = base + (size_t)y * W + xg;
                    nr = *(const float4*)(src + idx);
                    ng = *(const float4*)(src + idx + HW);
                    nb = *(const float4*)(src + idx + 2 * HW);
                }
            }
            if (i < NQUAD) {
                float4 m4 = make_float4(0.f, 0.f, 0.f, 0.f);
                if (valid) {
                    m4.x = detector(cr.x, cg.x, cb.x);
                    m4.y = detector(cr.y, cg.y, cb.y);
                    m4.z = detector(cr.z, cg.z, cb.z);
                    m4.w = detector(cr.w, cg.w, cb.w);
                }
                *(float4*)&mt[rcur][4 * qcur] = m4;
            }
            i = inext; valid = nvalid; rcur = rnext; qcur = qnext;
            cr = nr; cg = ng; cb = nb;
        }
    }
    __syncthreads();

    // ---- Phase 2: per-row horizontal pool via in-warp prefix scan ----
    for (int r = ty; r < HR; r += NW) {
        int c = 5 * tx;
        float v0 = mt[r][c + 0];
        float v1 = mt[r][c + 1];
        float v2 = mt[r][c + 2];
        float v3 = mt[r][c + 3];
        float v4 = mt[r][c + 4];
        v1 += v0; v2 += v1; v3 += v2; v4 += v3;   // local inclusive prefix
        float s = v4;
#pragma unroll
        for (int o = 1; o < 32; o <<= 1) {
            float n = __shfl_up_sync(0xffffffffu, s, o);
            if (tx >= o) s += n;
        }
        float excl = s - v4;
        mt[r][c + 0] = excl + v0;
        mt[r][c + 1] = excl + v1;
        mt[r][c + 2] = excl + v2;
        mt[r][c + 3] = excl + v3;
        mt[r][c + 4] = excl + v4;
        __syncwarp();
        float h0 = mt[r][tx + 15]       - mt[r][tx];
        float h1 = mt[r][tx + 32 + 15]  - mt[r][tx + 32];
        float h2 = mt[r][tx + 64 + 15]  - mt[r][tx + 64];
        float h3 = mt[r][tx + 96 + 15]  - mt[r][tx + 96];
        __syncwarp();
        mt[r][tx]      = h0;    // hsum row now lives at cols 0..127
        mt[r][tx + 32] = h1;
        mt[r][tx + 64] = h2;
        mt[r][tx + 96] = h3;
    }
    __syncthreads();

    // ---- Phase 3: vertical 15-tap running sum + per-pixel loss ----
    float vs0 = 0.f, vs1 = 0.f, vs2 = 0.f, vs3 = 0.f;
#pragma unroll
    for (int d = 0; d < KPOOL; ++d) {
        float4 h = *(float4*)&mt[yl0 + d][4 * tx];
        vs0 += h.x; vs1 += h.y; vs2 += h.z; vs3 += h.w;
    }

    float a1 = 0.0f, a2 = 0.0f, a3 = 0.0f;   // S1, sum(al1*wm), color

#pragma unroll
    for (int i = 0; i < 4; ++i) {
        // Prefetch next row before computing this one (distance 1).
        float4 np0, np1, np2, nt0, nt1, nt2, nq0, nq1, nq2;
        if (i < 3) {
            size_t nidx = base + (size_t)(y0 + yl0 + i + 1) * W + xc;
            np0 = ldcs4(pred + nidx);
            np1 = ldcs4(pred + nidx + HW);
            np2 = ldcs4(pred + nidx + 2 * HW);
            nt0 = ldcs4(tgt + nidx);
            nt1 = ldcs4(tgt + nidx + HW);
            nt2 = ldcs4(tgt + nidx + 2 * HW);
            nq0 = *(const float4*)(src + nidx);
            nq1 = *(const float4*)(src + nidx + HW);
            nq2 = *(const float4*)(src + nidx + 2 * HW);
        }

        const float* P0 = &p0.x; const float* P1 = &p1.x; const float* P2 = &p2.x;
        const float* T0 = &t0.x; const float* T1 = &t1.x; const float* T2 = &t2.x;
        const float* Q0 = &q0.x; const float* Q1 = &q1.x; const float* Q2 = &q2.x;
        float wmv[4] = {vs0, vs1, vs2, vs3};

#pragma unroll
        for (int k = 0; k < 4; ++k) {
            float d0 = P0[k] - T0[k], d1 = P1[k] - T1[k], d2 = P2[k] - T2[k];
            float al1 = fabsf(d0) + fabsf(d1) + fabsf(d2);
            float wm = wmv[k] * (1.0f / 225.0f);
            a1 += al1;
            a2 += al1 * wm;

            float st0 = T0[k] - Q0[k], st1 = T1[k] - Q1[k], st2 = T2[k] - Q2[k];
            float sp0 = P0[k] - Q0[k], sp1 = P1[k] - Q1[k], sp2 = P2[k] - Q2[k];
            float stm2 = fmaxf(st0 * st0 + st1 * st1 + st2 * st2, 1e-24f);
            float spm2 = fmaxf(sp0 * sp0 + sp1 * sp1 + sp2 * sp2, 1e-24f);
            float dot  = st0 * sp0 + st1 * sp1 + st2 * sp2;
            float ii = rsqrtf(fmaxf(stm2 * spm2, 1e-37f));  // 1/(stm*spm)
            float align = dot * ii;
            float magl  = fabsf(spm2 * ii - 1.0f);          // spm/stm
            a3 += wm * (1.0f - align + 0.5f * magl);
        }

        if (i < 3) {   // slide vertical window; rotate prefetched row in
            float4 add = *(float4*)&mt[yl0 + i + KPOOL][4 * tx];
            float4 sub = *(float4*)&mt[yl0 + i][4 * tx];
            vs0 += add.x - sub.x; vs1 += add.y - sub.y;
            vs2 += add.z - sub.z; vs3 += add.w - sub.w;
            p0 = np0; p1 = np1; p2 = np2;
            t0 = nt0; t1 = nt1; t2 = nt2;
            q0 = nq0; q1 = nq1; q2 = nq2;
        }
    }

    // ---- Reduction ----
#pragma unroll
    for (int o = 16; o > 0; o >>= 1) {
        a1 += __shfl_down_sync(0xffffffffu, a1, o);
        a2 += __shfl_down_sync(0xffffffffu, a2, o);
        a3 += __shfl_down_sync(0xffffffffu, a3, o);
    }
    __shared__ float red[NW][3];
    __shared__ bool amLast;
    if (tx == 0) { red[ty][0] = a1; red[ty][1] = a2; red[ty][2] = a3; }
    __syncthreads();
    if (ty == 0 && tx == 0) {
        float r1 = 0.0f, r2 = 0.0f, r3 = 0.0f;
#pragma unroll
        for (int w = 0; w < NW; ++w) { r1 += red[w][0]; r2 += red[w][1]; r3 += red[w][2]; }
        atomicAdd(&g_acc[0], (double)r1);
        atomicAdd(&g_acc[1], (double)r2);
        atomicAdd(&g_acc[2], (double)r3);
        __threadfence();
        unsigned tk = atomicAdd(&g_ticket, 1u);
        amLast = (tk == NBLOCKS - 1);
    }
    __syncthreads();

    // ---- Last block folds the final combine ----
    if (amLast && ty == 0 && tx == 0) {
        const double N_ALL = (double)B * C * H * W;
        const double N_PIX = (double)B * H * W;
        double S1 = g_acc[0], S2w = g_acc[1], S3 = g_acc[2];
        // l1 + 3*win_l1 + 2*color ; win_l1 = (S1 + 4*S2w)/N_ALL
        double total = 4.0 * S1 / N_ALL + 12.0 * S2w / N_ALL + 2.0 * S3 / N_PIX;
        out[0] = (float)total;
        g_acc[0] = 0.0; g_acc[1] = 0.0; g_acc[2] = 0.0;
        g_ticket = 0u;
    }
}

extern "C" void kernel_launch(void* const* d_in, const int* in_sizes, int n_in,
                              void* d_out, int out_size) {
    const float* pred = (const float*)d_in[0];
    const float* tgt  = (const float*)d_in[1];
    const float* src  = (const float*)d_in[2];
    float* out = (float*)d_out;

    dim3 grid(W / TXV, H / TY, B);
    dim3 blk(32, NW);
    k_fused<<<grid, blk>>>(pred, tgt, src, out);
}

// round 15
// speedup vs baseline: 1.9087x; 1.0356x over previous
#include <cuda_runtime.h>
#include <math.h>

#define B 16
#define C 3
#define H 512
#define W 512
#define HW (H*W)
#define CHW (C*H*W)
#define KPOOL 15

#define TXV 128      // output tile width
#define TY  32       // output tile height
#define NW  8        // warps per block
#define HR  46       // halo rows (TY + 14)
#define MW  160      // m-tile width (TXV + 16 halo cols = 5*32)
#define NQUAD (HR * (MW/4))          // 1840 detector quads
#define NBLOCKS ((W/TXV)*(H/TY)*B)   // 1024

// scalar accumulators: S1 (l1), S2w (al1*wm), S3 (color)
__device__ double g_acc[3];
__device__ unsigned g_ticket;

__device__ __forceinline__ float fast_tanh(float x) {
    float r;
    asm("tanh.approx.f32 %0, %1;" : "=f"(r) : "f"(x));
    return r;
}
__device__ __forceinline__ float fsig2(float half_x) {   // sigmoid(2*half_x)
    return fmaf(0.5f, fast_tanh(half_x), 0.5f);
}

__device__ __forceinline__ float detector(float r, float g, float b) {
    float lum = 0.299f * r + 0.587f * g + 0.114f * b;
    float mx = fmaxf(r, fmaxf(g, b));
    float mn = fminf(r, fminf(g, b));
    // src rescaled to [0,1]: sigmoid(10*lum-3) * sigmoid(3-10*(mx-mn))
    return fsig2(5.0f * lum - 1.5f) * fsig2(1.5f - 5.0f * (mx - mn));
}

__device__ __forceinline__ float4 ldcs4(const float* p) {
    return __ldcs((const float4*)p);
}
__device__ __forceinline__ float4 ldcg4(const float* p) {
    return __ldcg((const float4*)p);
}

__global__ __launch_bounds__(256, 4) void k_fused(const float* __restrict__ pred,
                                                  const float* __restrict__ tgt,
                                                  const float* __restrict__ src,
                                                  float* __restrict__ out) {
    const int tx = threadIdx.x;           // 0..31
    const int ty = threadIdx.y;           // 0..7 (warp id)
    const int tid = ty * 32 + tx;
    const int b  = blockIdx.z;
    const int x0 = blockIdx.x * TXV;
    const int y0 = blockIdx.y * TY;
    const int xb = x0 - 8;                // m-tile col 0 == global x xb

    __shared__ float mt[HR][MW];          // detector map -> hsum (in place)

    const size_t base = (size_t)b * CHW;
    const int yl0 = 4 * ty;
    const int xc  = x0 + 4 * tx;

    // ---- Pre-issue phase-3 row-0 loads: in flight through phases 1-2 ----
    const size_t idx0 = base + (size_t)(y0 + yl0) * W + xc;
    float4 p0 = ldcs4(pred + idx0);
    float4 p1 = ldcs4(pred + idx0 + HW);
    float4 p2 = ldcs4(pred + idx0 + 2 * HW);
    float4 t0 = ldcs4(tgt + idx0);
    float4 t1 = ldcs4(tgt + idx0 + HW);
    float4 t2 = ldcs4(tgt + idx0 + 2 * HW);
    float4 q0 = *(const float4*)(src + idx0);
    float4 q1 = *(const float4*)(src + idx0 + HW);
    float4 q2 = *(const float4*)(src + idx0 + 2 * HW);

    // ---- Phase 1: detector map with halo (software-pipelined, L1-bypass) ----
    {
        int i = tid;
        float4 cr, cg, cb;
        bool valid = false;
        int rcur = 0, qcur = 0;
        {
            int r = i / (MW / 4);
            int q = i - r * (MW / 4);
            int y = y0 + r - 7;
            int xg = xb + 4 * q;
            rcur = r; qcur = q;
            valid = ((unsigned)y < H && (unsigned)xg < W);
            if (valid) {
                size_t idx = base + (size_t)y * W + xg;
                cr = ldcg4(src + idx);
                cg = ldcg4(src + idx + HW);
                cb = ldcg4(src + idx + 2 * HW);
            }
        }
#pragma unroll
        for (int step = 0; step < 8; ++step) {
            int inext = i + 256;
            float4 nr, ng, nb;
            bool nvalid = false;
            int rnext = 0, qnext = 0;
            if (inext < NQUAD) {
                int r = inext / (MW / 4);
                int q = inext - r * (MW / 4);
                int y = y0 + r - 7;
                int xg = xb + 4 * q;
                rnext = r; qnext = q;
                nvalid = ((unsigned)y < H && (unsigned)xg < W);
                if (nvalid) {
                    size_t idx = base + (size_t)y * W + xg;
                    nr = ldcg4(src + idx);
                    ng = ldcg4(src + idx + HW);
                    nb = ldcg4(src + idx + 2 * HW);
                }
            }
            if (i < NQUAD) {
                float4 m4 = make_float4(0.f, 0.f, 0.f, 0.f);
                if (valid) {
                    m4.x = detector(cr.x, cg.x, cb.x);
                    m4.y = detector(cr.y, cg.y, cb.y);
                    m4.z = detector(cr.z, cg.z, cb.z);
                    m4.w = detector(cr.w, cg.w, cb.w);
                }
                *(float4*)&mt[rcur][4 * qcur] = m4;
            }
            i = inext; valid = nvalid; rcur = rnext; qcur = qnext;
            cr = nr; cg = ng; cb = nb;
        }
    }
    __syncthreads();

    // ---- Phase 2: horizontal pool, prefix kept in registers, +15 via shfl ----
    // c = 5*lane + j  =>  c+15 = 5*(lane+3) + j : same j slot, 3 lanes up.
    for (int r = ty; r < HR; r += NW) {
        int c = 5 * tx;
        float v0 = mt[r][c + 0];
        float v1 = mt[r][c + 1];
        float v2 = mt[r][c + 2];
        float v3 = mt[r][c + 3];
        float v4 = mt[r][c + 4];
        v1 += v0; v2 += v1; v3 += v2; v4 += v3;   // local inclusive prefix
        float s = v4;
#pragma unroll
        for (int o = 1; o < 32; o <<= 1) {
            float n = __shfl_up_sync(0xffffffffu, s, o);
            if (tx >= o) s += n;
        }
        float excl = s - v4;
        float P0 = excl + v0, P1 = excl + v1, P2 = excl + v2,
              P3 = excl + v3, P4 = excl + v4;
        // hsum[c] = P[c+15] - P[c]
        float h0 = __shfl_down_sync(0xffffffffu, P0, 3) - P0;
        float h1 = __shfl_down_sync(0xffffffffu, P1, 3) - P1;
        float h2 = __shfl_down_sync(0xffffffffu, P2, 3) - P2;
        float h3 = __shfl_down_sync(0xffffffffu, P3, 3) - P3;
        float h4 = __shfl_down_sync(0xffffffffu, P4, 3) - P4;
        // store only output cols 0..127 (lane reads precede writes: no hazard)
        if (c + 0 < TXV) mt[r][c + 0] = h0;
        if (c + 1 < TXV) mt[r][c + 1] = h1;
        if (c + 2 < TXV) mt[r][c + 2] = h2;
        if (c + 3 < TXV) mt[r][c + 3] = h3;
        if (c + 4 < TXV) mt[r][c + 4] = h4;
    }
    __syncthreads();

    // ---- Phase 3: vertical 15-tap running sum + per-pixel loss ----
    float vs0 = 0.f, vs1 = 0.f, vs2 = 0.f, vs3 = 0.f;
#pragma unroll
    for (int d = 0; d < KPOOL; ++d) {
        float4 h = *(float4*)&mt[yl0 + d][4 * tx];
        vs0 += h.x; vs1 += h.y; vs2 += h.z; vs3 += h.w;
    }

    float a1 = 0.0f, a2 = 0.0f, a3 = 0.0f;   // S1, sum(al1*wm), color

#pragma unroll
    for (int i = 0; i < 4; ++i) {
        // Prefetch next row before computing this one (distance 1).
        float4 np0, np1, np2, nt0, nt1, nt2, nq0, nq1, nq2;
        if (i < 3) {
            size_t nidx = base + (size_t)(y0 + yl0 + i + 1) * W + xc;
            np0 = ldcs4(pred + nidx);
            np1 = ldcs4(pred + nidx + HW);
            np2 = ldcs4(pred + nidx + 2 * HW);
            nt0 = ldcs4(tgt + nidx);
            nt1 = ldcs4(tgt + nidx + HW);
            nt2 = ldcs4(tgt + nidx + 2 * HW);
            nq0 = *(const float4*)(src + nidx);
            nq1 = *(const float4*)(src + nidx + HW);
            nq2 = *(const float4*)(src + nidx + 2 * HW);
        }

        const float* P0 = &p0.x; const float* P1 = &p1.x; const float* P2 = &p2.x;
        const float* T0 = &t0.x; const float* T1 = &t1.x; const float* T2 = &t2.x;
        const float* Q0 = &q0.x; const float* Q1 = &q1.x; const float* Q2 = &q2.x;
        float wmv[4] = {vs0, vs1, vs2, vs3};

#pragma unroll
        for (int k = 0; k < 4; ++k) {
            float d0 = P0[k] - T0[k], d1 = P1[k] - T1[k], d2 = P2[k] - T2[k];
            float al1 = fabsf(d0) + fabsf(d1) + fabsf(d2);
            float wm = wmv[k] * (1.0f / 225.0f);
            a1 += al1;
            a2 += al1 * wm;

            float st0 = T0[k] - Q0[k], st1 = T1[k] - Q1[k], st2 = T2[k] - Q2[k];
            float sp0 = P0[k] - Q0[k], sp1 = P1[k] - Q1[k], sp2 = P2[k] - Q2[k];
            float stm2 = fmaxf(st0 * st0 + st1 * st1 + st2 * st2, 1e-24f);
            float spm2 = fmaxf(sp0 * sp0 + sp1 * sp1 + sp2 * sp2, 1e-24f);
            float dot  = st0 * sp0 + st1 * sp1 + st2 * sp2;
            float ii = rsqrtf(fmaxf(stm2 * spm2, 1e-37f));  // 1/(stm*spm)
            float align = dot * ii;
            float magl  = fabsf(spm2 * ii - 1.0f);          // spm/stm
            a3 += wm * (1.0f - align + 0.5f * magl);
        }

        if (i < 3) {   // slide vertical window; rotate prefetched row in
            float4 add = *(float4*)&mt[yl0 + i + KPOOL][4 * tx];
            float4 sub = *(float4*)&mt[yl0 + i][4 * tx];
            vs0 += add.x - sub.x; vs1 += add.y - sub.y;
            vs2 += add.z - sub.z; vs3 += add.w - sub.w;
            p0 = np0; p1 = np1; p2 = np2;
            t0 = nt0; t1 = nt1; t2 = nt2;
            q0 = nq0; q1 = nq1; q2 = nq2;
        }
    }

    // ---- Reduction ----
#pragma unroll
    for (int o = 16; o > 0; o >>= 1) {
        a1 += __shfl_down_sync(0xffffffffu, a1, o);
        a2 += __shfl_down_sync(0xffffffffu, a2, o);
        a3 += __shfl_down_sync(0xffffffffu, a3, o);
    }
    __shared__ float red[NW][3];
    __shared__ bool amLast;
    if (tx == 0) { red[ty][0] = a1; red[ty][1] = a2; red[ty][2] = a3; }
    __syncthreads();
    if (ty == 0 && tx == 0) {
        float r1 = 0.0f, r2 = 0.0f, r3 = 0.0f;
#pragma unroll
        for (int w = 0; w < NW; ++w) { r1 += red[w][0]; r2 += red[w][1]; r3 += red[w][2]; }
        atomicAdd(&g_acc[0], (double)r1);
        atomicAdd(&g_acc[1], (double)r2);
        atomicAdd(&g_acc[2], (double)r3);
        __threadfence();
        unsigned tk = atomicAdd(&g_ticket, 1u);
        amLast = (tk == NBLOCKS - 1);
    }
    __syncthreads();

    // ---- Last block folds the final combine ----
    if (amLast && ty == 0 && tx == 0) {
        const double N_ALL = (double)B * C * H * W;
        const double N_PIX = (double)B * H * W;
        double S1 = g_acc[0], S2w = g_acc[1], S3 = g_acc[2];
        // l1 + 3*win_l1 + 2*color ; win_l1 = (S1 + 4*S2w)/N_ALL
        double total = 4.0 * S1 / N_ALL + 12.0 * S2w / N_ALL + 2.0 * S3 / N_PIX;
        out[0] = (float)total;
        g_acc[0] = 0.0; g_acc[1] = 0.0; g_acc[2] = 0.0;
        g_ticket = 0u;
    }
}

extern "C" void kernel_launch(void* const* d_in, const int* in_sizes, int n_in,
                              void* d_out, int out_size) {
    const float* pred = (const float*)d_in[0];
    const float* tgt  = (const float*)d_in[1];
    const float* src  = (const float*)d_in[2];
    float* out = (float*)d_out;

    dim3 grid(W / TXV, H / TY, B);
    dim3 blk(32, NW);
    k_fused<<<grid, blk>>>(pred, tgt, src, out);
}